// round 1
// baseline (speedup 1.0000x reference)
#include <cuda_runtime.h>
#include <cuda_bf16.h>
#include <math.h>

// Problem constants
constexpr int B_ = 2, T_ = 2048, E_ = 1024, H_ = 16, HD_ = 64, FFDIM = 4096, L_ = 4;
constexpr int M_ = B_ * T_;           // 4096 token rows
constexpr int QKVW = 3 * E_;          // 3072

// Scratch (device globals; no allocations allowed)
__device__ float g_x[M_ * E_];        // residual stream
__device__ float g_qkv[M_ * 3 * E_];  // fused qkv
__device__ float g_attn[M_ * E_];     // attention output (pre-proj)
__device__ float g_h[M_ * FFDIM];     // MLP hidden

__device__ __forceinline__ float gelu_tanh(float x) {
    // JAX jax.nn.gelu default (approximate=True)
    float x3 = x * x * x;
    return 0.5f * x * (1.0f + tanhf(0.7978845608028654f * (x + 0.044715f * x3)));
}

// ---------------------------------------------------------------------------
// Tiled SGEMM: C[M,N] = epilogue(A[M,K] @ W[K,N] + bias[N]) (+ res[M,N])
// 128x128 block tile, BK=16, 256 threads, 8x8 register micro-tile.
// All dims are multiples of the tile sizes for this problem -> no bounds checks.
// ---------------------------------------------------------------------------
template <int ACT, bool RES>
__global__ void __launch_bounds__(256) gemm128(
    const float* __restrict__ A, const float* __restrict__ W,
    const float* __restrict__ bias, const float* __restrict__ res,
    float* __restrict__ C, int M, int N, int K)
{
    __shared__ float As[16][128];   // transposed A tile: As[k][m]
    __shared__ float Bs[16][128];   // Bs[k][n]

    const int bm = blockIdx.y * 128;
    const int bn = blockIdx.x * 128;
    const int tid = threadIdx.x;
    const int tx = tid & 15;   // n micro index
    const int ty = tid >> 4;   // m micro index

    float acc[8][8];
#pragma unroll
    for (int i = 0; i < 8; i++)
#pragma unroll
        for (int j = 0; j < 8; j++) acc[i][j] = 0.0f;

    for (int k0 = 0; k0 < K; k0 += 16) {
        // Load A tile (128 rows x 16 k), transposed into As; 512 float4 total
#pragma unroll
        for (int t = 0; t < 2; t++) {
            int f = tid + t * 256;
            int ar = f >> 2;             // 0..127
            int akq = (f & 3) << 2;      // 0,4,8,12
            float4 av = *reinterpret_cast<const float4*>(
                &A[(size_t)(bm + ar) * K + k0 + akq]);
            As[akq + 0][ar] = av.x;
            As[akq + 1][ar] = av.y;
            As[akq + 2][ar] = av.z;
            As[akq + 3][ar] = av.w;

            int bkr = f >> 5;            // 0..15
            int bnq = (f & 31) << 2;     // 0..124
            *reinterpret_cast<float4*>(&Bs[bkr][bnq]) =
                *reinterpret_cast<const float4*>(
                    &W[(size_t)(k0 + bkr) * N + bn + bnq]);
        }
        __syncthreads();

#pragma unroll
        for (int k = 0; k < 16; k++) {
            float a[8], b[8];
            *reinterpret_cast<float4*>(&a[0]) = *reinterpret_cast<float4*>(&As[k][ty * 8]);
            *reinterpret_cast<float4*>(&a[4]) = *reinterpret_cast<float4*>(&As[k][ty * 8 + 4]);
            *reinterpret_cast<float4*>(&b[0]) = *reinterpret_cast<float4*>(&Bs[k][tx * 8]);
            *reinterpret_cast<float4*>(&b[4]) = *reinterpret_cast<float4*>(&Bs[k][tx * 8 + 4]);
#pragma unroll
            for (int i = 0; i < 8; i++)
#pragma unroll
                for (int j = 0; j < 8; j++)
                    acc[i][j] = fmaf(a[i], b[j], acc[i][j]);
        }
        __syncthreads();
    }

    // Epilogue: bias (+GELU) (+residual)
#pragma unroll
    for (int i = 0; i < 8; i++) {
        const int row = bm + ty * 8 + i;
#pragma unroll
        for (int j = 0; j < 8; j++) {
            const int col = bn + tx * 8 + j;
            float val = acc[i][j] + bias[col];
            if (ACT == 1) val = gelu_tanh(val);
            if (RES) val += res[(size_t)row * N + col];
            C[(size_t)row * N + col] = val;
        }
    }
}

// ---------------------------------------------------------------------------
// Fused flash attention (non-causal), fp32, online softmax.
// qkv layout: [B, T, 3E] with q at col h*64+d, k at E+h*64+d, v at 2E+h*64+d.
// Grid: (T/32, B*H). Block: 256 threads = 8 warps, each warp owns 4 q rows.
// out: [B, T, E] with head-concat columns (h*64+d) — matches the reference
// transpose(0,2,1,3).reshape(B,T,E).
// ---------------------------------------------------------------------------
__global__ void __launch_bounds__(256) attn_kernel(
    const float* __restrict__ qkv, float* __restrict__ out)
{
    __shared__ float Qs[32][64];     // q tile (scale folded in)
    __shared__ float KV[64][65];     // K tile, then V tile (padded rows)
    __shared__ float Ps[32][64];     // softmax probs for this k-tile

    const int b = blockIdx.y >> 4;
    const int h = blockIdx.y & 15;
    const int q0 = blockIdx.x << 5;
    const int tid = threadIdx.x;
    const int lane = tid & 31;
    const int warp = tid >> 5;
    const int r0 = warp * 4;
    const float* base = qkv + (size_t)b * T_ * QKVW;
    const int hc = h * 64;

    // Load Q tile (32 rows x 64), scaled by 1/sqrt(HD)=0.125
#pragma unroll
    for (int t = 0; t < 2; t++) {
        int f = tid + t * 256;            // 512 float4
        int r = f >> 4;
        int dq = (f & 15) << 2;
        float4 v = *reinterpret_cast<const float4*>(
            &base[(size_t)(q0 + r) * QKVW + hc + dq]);
        Qs[r][dq + 0] = v.x * 0.125f;
        Qs[r][dq + 1] = v.y * 0.125f;
        Qs[r][dq + 2] = v.z * 0.125f;
        Qs[r][dq + 3] = v.w * 0.125f;
    }

    float m[4], lsum[4], acc[4][2];
#pragma unroll
    for (int i = 0; i < 4; i++) {
        m[i] = -1e30f; lsum[i] = 0.0f; acc[i][0] = 0.0f; acc[i][1] = 0.0f;
    }

    for (int kt = 0; kt < T_; kt += 64) {
        __syncthreads();   // Qs ready (1st iter); KV free again (later iters)
        // Load K tile: 64 rows x 64 d
#pragma unroll
        for (int t = 0; t < 4; t++) {
            int f = tid + t * 256;        // 1024 float4
            int r = f >> 4;
            int dq = (f & 15) << 2;
            float4 v = *reinterpret_cast<const float4*>(
                &base[(size_t)(kt + r) * QKVW + E_ + hc + dq]);
            KV[r][dq + 0] = v.x; KV[r][dq + 1] = v.y;
            KV[r][dq + 2] = v.z; KV[r][dq + 3] = v.w;
        }
        __syncthreads();

        // S = Q @ K^T  (each lane: k cols lane and lane+32, 4 rows)
        float s[4][2];
#pragma unroll
        for (int i = 0; i < 4; i++) { s[i][0] = 0.0f; s[i][1] = 0.0f; }
#pragma unroll 8
        for (int d = 0; d < 64; d++) {
            float k0v = KV[lane][d];
            float k1v = KV[lane + 32][d];
#pragma unroll
            for (int i = 0; i < 4; i++) {
                float q = Qs[r0 + i][d];
                s[i][0] = fmaf(q, k0v, s[i][0]);
                s[i][1] = fmaf(q, k1v, s[i][1]);
            }
        }

        // Online softmax update per row
#pragma unroll
        for (int i = 0; i < 4; i++) {
            float rm = fmaxf(s[i][0], s[i][1]);
#pragma unroll
            for (int o = 16; o > 0; o >>= 1)
                rm = fmaxf(rm, __shfl_xor_sync(0xffffffffu, rm, o));
            float mnew = fmaxf(m[i], rm);
            float corr = __expf(m[i] - mnew);
            float p0 = __expf(s[i][0] - mnew);
            float p1 = __expf(s[i][1] - mnew);
            float ps = p0 + p1;
#pragma unroll
            for (int o = 16; o > 0; o >>= 1)
                ps += __shfl_xor_sync(0xffffffffu, ps, o);
            lsum[i] = lsum[i] * corr + ps;
            acc[i][0] *= corr;
            acc[i][1] *= corr;
            Ps[r0 + i][lane] = p0;
            Ps[r0 + i][lane + 32] = p1;
            m[i] = mnew;
        }
        __syncthreads();   // all warps done reading K from KV

        // Load V tile into KV
#pragma unroll
        for (int t = 0; t < 4; t++) {
            int f = tid + t * 256;
            int r = f >> 4;
            int dq = (f & 15) << 2;
            float4 v = *reinterpret_cast<const float4*>(
                &base[(size_t)(kt + r) * QKVW + 2 * E_ + hc + dq]);
            KV[r][dq + 0] = v.x; KV[r][dq + 1] = v.y;
            KV[r][dq + 2] = v.z; KV[r][dq + 3] = v.w;
        }
        __syncthreads();

        // acc += P @ V
#pragma unroll 8
        for (int k = 0; k < 64; k++) {
            float v0 = KV[k][lane];
            float v1 = KV[k][lane + 32];
#pragma unroll
            for (int i = 0; i < 4; i++) {
                float p = Ps[r0 + i][k];
                acc[i][0] = fmaf(p, v0, acc[i][0]);
                acc[i][1] = fmaf(p, v1, acc[i][1]);
            }
        }
    }

    // Normalize and write out
#pragma unroll
    for (int i = 0; i < 4; i++) {
        float inv = 1.0f / lsum[i];
        size_t orow = ((size_t)b * T_ + q0 + r0 + i) * E_ + hc;
        out[orow + lane]      = acc[i][0] * inv;
        out[orow + lane + 32] = acc[i][1] * inv;
    }
}

// ---------------------------------------------------------------------------
// Orchestration: 4 layers x (QKV gemm, attention, proj+res, MLP1(gelu), MLP2+res)
// All launches on the default stream; graph-capturable; no allocations.
// ---------------------------------------------------------------------------
extern "C" void kernel_launch(void* const* d_in, const int* in_sizes, int n_in,
                              void* d_out, int out_size)
{
    const float* x_in  = (const float*)d_in[0];
    const float* Wqkv  = (const float*)d_in[1];
    const float* bqkv  = (const float*)d_in[2];
    const float* Wproj = (const float*)d_in[3];
    const float* bproj = (const float*)d_in[4];
    const float* W1    = (const float*)d_in[5];
    const float* b1    = (const float*)d_in[6];
    const float* W2    = (const float*)d_in[7];
    const float* b2    = (const float*)d_in[8];
    float* out = (float*)d_out;

    float *gx, *gqkv, *gattn, *gh;
    cudaGetSymbolAddress((void**)&gx, g_x);
    cudaGetSymbolAddress((void**)&gqkv, g_qkv);
    cudaGetSymbolAddress((void**)&gattn, g_attn);
    cudaGetSymbolAddress((void**)&gh, g_h);

    dim3 blk(256);
    for (int l = 0; l < L_; l++) {
        const float* xcur = (l == 0) ? x_in : gx;

        // QKV projection: [M,E] @ [E,3E] + b
        gemm128<0, false><<<dim3(QKVW / 128, M_ / 128), blk>>>(
            xcur, Wqkv + (size_t)l * E_ * QKVW, bqkv + (size_t)l * QKVW,
            nullptr, gqkv, M_, QKVW, E_);

        // Fused flash attention
        attn_kernel<<<dim3(T_ / 32, B_ * H_), blk>>>(gqkv, gattn);

        // Output projection + residual: x = x + attn @ Wproj + bproj
        gemm128<0, true><<<dim3(E_ / 128, M_ / 128), blk>>>(
            gattn, Wproj + (size_t)l * E_ * E_, bproj + (size_t)l * E_,
            xcur, gx, M_, E_, E_);

        // MLP up + GELU: h = gelu(x @ W1 + b1)
        gemm128<1, false><<<dim3(FFDIM / 128, M_ / 128), blk>>>(
            gx, W1 + (size_t)l * E_ * FFDIM, b1 + (size_t)l * FFDIM,
            nullptr, gh, M_, FFDIM, E_);

        // MLP down + residual: x = x + h @ W2 + b2  (last layer writes d_out)
        float* dst = (l == L_ - 1) ? out : gx;
        gemm128<0, true><<<dim3(E_ / 128, M_ / 128), blk>>>(
            gh, W2 + (size_t)l * FFDIM * E_, b2 + (size_t)l * E_,
            gx, dst, M_, E_, FFDIM);
    }
}

// round 2
// speedup vs baseline: 1.6039x; 1.6039x over previous
#include <cuda_runtime.h>
#include <cuda_bf16.h>
#include <math.h>

// Problem constants
constexpr int B_ = 2, T_ = 2048, E_ = 1024, H_ = 16, FFDIM = 4096, L_ = 4;
constexpr int M_ = B_ * T_;           // 4096 token rows
constexpr int QKVW = 3 * E_;          // 3072

// Scratch (device globals; no allocations allowed)
__device__ float g_x[M_ * E_];        // residual stream
__device__ float g_qkv[M_ * 3 * E_];  // fused qkv
__device__ float g_attn[M_ * E_];     // attention output (pre-proj)
__device__ float g_h[M_ * FFDIM];     // MLP hidden

__device__ __forceinline__ float gelu_tanh(float x) {
    float x3 = x * x * x;
    return 0.5f * x * (1.0f + tanhf(0.7978845608028654f * (x + 0.044715f * x3)));
}

// pack two fp32 into bf16x2 (lo goes to low 16 bits / element 0 in memory)
__device__ __forceinline__ unsigned pack2(float lo, float hi) {
    unsigned r;
    asm("cvt.rn.bf16x2.f32 %0, %1, %2;" : "=r"(r) : "f"(hi), "f"(lo));
    return r;
}

__device__ __forceinline__ void ldmx4(unsigned* r, unsigned addr) {
    asm volatile("ldmatrix.sync.aligned.m8n8.x4.shared.b16 {%0,%1,%2,%3}, [%4];"
        : "=r"(r[0]), "=r"(r[1]), "=r"(r[2]), "=r"(r[3]) : "r"(addr));
}
__device__ __forceinline__ void ldmx4t(unsigned* r, unsigned addr) {
    asm volatile("ldmatrix.sync.aligned.m8n8.x4.trans.shared.b16 {%0,%1,%2,%3}, [%4];"
        : "=r"(r[0]), "=r"(r[1]), "=r"(r[2]), "=r"(r[3]) : "r"(addr));
}
__device__ __forceinline__ void mma16816(float* d, const unsigned* a, const unsigned* b) {
    asm volatile("mma.sync.aligned.m16n8k16.row.col.f32.bf16.bf16.f32 "
        "{%0,%1,%2,%3}, {%4,%5,%6,%7}, {%8,%9}, {%0,%1,%2,%3};"
        : "+f"(d[0]), "+f"(d[1]), "+f"(d[2]), "+f"(d[3])
        : "r"(a[0]), "r"(a[1]), "r"(a[2]), "r"(a[3]), "r"(b[0]), "r"(b[1]));
}

// ---------------------------------------------------------------------------
// Tensor-core GEMM with bf16 3-term split (hi*hi + hi*lo + lo*hi), fp32 accum.
// C[M,N] = epilogue(A[M,K] @ W[K,N] + bias[N]) (+ res[M,N])
// 128x128 tile, BK=32, 256 threads (8 warps, 64x32 warp tiles).
// fp32 gmem loads, inline bf16 hi/lo conversion into smem, reg-prefetch pipe.
// ---------------------------------------------------------------------------
template <int ACT, bool RES>
__global__ void __launch_bounds__(256) gemm_mma(
    const float* __restrict__ A, const float* __restrict__ W,
    const float* __restrict__ bias, const float* __restrict__ res,
    float* __restrict__ C, int M, int N, int K)
{
    __shared__ __align__(16) unsigned short As_h[128][40];   // [m][k], pad 8
    __shared__ __align__(16) unsigned short As_l[128][40];
    __shared__ __align__(16) unsigned short Bs_h[32][136];   // [k][n], pad 8
    __shared__ __align__(16) unsigned short Bs_l[32][136];

    const int bm = blockIdx.y * 128;
    const int bn = blockIdx.x * 128;
    const int tid = threadIdx.x;
    const int lane = tid & 31;
    const int warp = tid >> 5;
    const int wm = (warp >> 2) * 64;   // warp m offset (0/64)
    const int wn = (warp & 3) * 32;    // warp n offset (0..96)

    float acc[4][4][4];
#pragma unroll
    for (int i = 0; i < 4; i++)
#pragma unroll
        for (int j = 0; j < 4; j++)
#pragma unroll
            for (int t = 0; t < 4; t++) acc[i][j][t] = 0.0f;

    float4 Ar[4], Br[4];

    auto load_tile = [&](int k0) {
#pragma unroll
        for (int i = 0; i < 4; i++) {
            int f = tid + 256 * i;
            int r = f >> 3, kc = (f & 7) << 2;
            Ar[i] = *reinterpret_cast<const float4*>(&A[(size_t)(bm + r) * K + k0 + kc]);
        }
#pragma unroll
        for (int i = 0; i < 4; i++) {
            int f = tid + 256 * i;
            int r = f >> 5, nc = (f & 31) << 2;
            Br[i] = *reinterpret_cast<const float4*>(&W[(size_t)(k0 + r) * N + bn + nc]);
        }
    };

    auto stage_tile = [&]() {
#pragma unroll
        for (int i = 0; i < 4; i++) {
            int f = tid + 256 * i;
            int r = f >> 3, kc = (f & 7) << 2;
            float4 v = Ar[i];
            unsigned h0 = pack2(v.x, v.y), h1 = pack2(v.z, v.w);
            float rx = __uint_as_float(h0 << 16), ry = __uint_as_float(h0 & 0xFFFF0000u);
            float rz = __uint_as_float(h1 << 16), rw = __uint_as_float(h1 & 0xFFFF0000u);
            unsigned l0 = pack2(v.x - rx, v.y - ry), l1 = pack2(v.z - rz, v.w - rw);
            *reinterpret_cast<uint2*>(&As_h[r][kc]) = make_uint2(h0, h1);
            *reinterpret_cast<uint2*>(&As_l[r][kc]) = make_uint2(l0, l1);
        }
#pragma unroll
        for (int i = 0; i < 4; i++) {
            int f = tid + 256 * i;
            int r = f >> 5, nc = (f & 31) << 2;
            float4 v = Br[i];
            unsigned h0 = pack2(v.x, v.y), h1 = pack2(v.z, v.w);
            float rx = __uint_as_float(h0 << 16), ry = __uint_as_float(h0 & 0xFFFF0000u);
            float rz = __uint_as_float(h1 << 16), rw = __uint_as_float(h1 & 0xFFFF0000u);
            unsigned l0 = pack2(v.x - rx, v.y - ry), l1 = pack2(v.z - rz, v.w - rw);
            *reinterpret_cast<uint2*>(&Bs_h[r][nc]) = make_uint2(h0, h1);
            *reinterpret_cast<uint2*>(&Bs_l[r][nc]) = make_uint2(l0, l1);
        }
    };

    const int nstages = K >> 5;   // K/32
    load_tile(0);
    stage_tile();
    __syncthreads();

    for (int s = 0; s < nstages; s++) {
        if (s + 1 < nstages) load_tile((s + 1) << 5);

#pragma unroll
        for (int ks = 0; ks < 32; ks += 16) {
            unsigned bh[2][4], bl[2][4];
#pragma unroll
            for (int g = 0; g < 2; g++) {
                unsigned a0 = (unsigned)__cvta_generic_to_shared(
                    &Bs_h[ks + (lane & 15)][wn + g * 16 + ((lane >> 4) << 3)]);
                ldmx4t(bh[g], a0);
                unsigned a1 = (unsigned)__cvta_generic_to_shared(
                    &Bs_l[ks + (lane & 15)][wn + g * 16 + ((lane >> 4) << 3)]);
                ldmx4t(bl[g], a1);
            }
#pragma unroll
            for (int ma = 0; ma < 4; ma++) {
                unsigned ah[4], al[4];
                unsigned a0 = (unsigned)__cvta_generic_to_shared(
                    &As_h[wm + ma * 16 + (lane & 15)][ks + ((lane >> 4) << 3)]);
                ldmx4(ah, a0);
                unsigned a1 = (unsigned)__cvta_generic_to_shared(
                    &As_l[wm + ma * 16 + (lane & 15)][ks + ((lane >> 4) << 3)]);
                ldmx4(al, a1);
#pragma unroll
                for (int na = 0; na < 4; na++) {
                    const unsigned* bhp = &bh[na >> 1][(na & 1) * 2];
                    const unsigned* blp = &bl[na >> 1][(na & 1) * 2];
                    mma16816(acc[ma][na], ah, bhp);
                    mma16816(acc[ma][na], ah, blp);
                    mma16816(acc[ma][na], al, bhp);
                }
            }
        }

        if (s + 1 < nstages) {
            __syncthreads();
            stage_tile();
            __syncthreads();
        }
    }

    // Epilogue: bias (+GELU) (+residual); fragment layout writes
#pragma unroll
    for (int ma = 0; ma < 4; ma++) {
        int r0 = bm + wm + ma * 16 + (lane >> 2);
#pragma unroll
        for (int na = 0; na < 4; na++) {
            int c0 = bn + wn + na * 8 + ((lane & 3) << 1);
            float b0v = bias[c0], b1v = bias[c0 + 1];
            float v00 = acc[ma][na][0] + b0v, v01 = acc[ma][na][1] + b1v;
            float v10 = acc[ma][na][2] + b0v, v11 = acc[ma][na][3] + b1v;
            if (ACT == 1) {
                v00 = gelu_tanh(v00); v01 = gelu_tanh(v01);
                v10 = gelu_tanh(v10); v11 = gelu_tanh(v11);
            }
            if (RES) {
                v00 += res[(size_t)r0 * N + c0];
                v01 += res[(size_t)r0 * N + c0 + 1];
                v10 += res[(size_t)(r0 + 8) * N + c0];
                v11 += res[(size_t)(r0 + 8) * N + c0 + 1];
            }
            float2 p0 = make_float2(v00, v01);
            float2 p1 = make_float2(v10, v11);
            *reinterpret_cast<float2*>(&C[(size_t)r0 * N + c0]) = p0;
            *reinterpret_cast<float2*>(&C[(size_t)(r0 + 8) * N + c0]) = p1;
        }
    }
}

// ---------------------------------------------------------------------------
// Fused flash attention (non-causal), fp32, online softmax. (unchanged, verified)
// ---------------------------------------------------------------------------
__global__ void __launch_bounds__(256) attn_kernel(
    const float* __restrict__ qkv, float* __restrict__ out)
{
    __shared__ float Qs[32][64];
    __shared__ float KV[64][65];
    __shared__ float Ps[32][64];

    const int b = blockIdx.y >> 4;
    const int h = blockIdx.y & 15;
    const int q0 = blockIdx.x << 5;
    const int tid = threadIdx.x;
    const int lane = tid & 31;
    const int warp = tid >> 5;
    const int r0 = warp * 4;
    const float* base = qkv + (size_t)b * T_ * QKVW;
    const int hc = h * 64;

#pragma unroll
    for (int t = 0; t < 2; t++) {
        int f = tid + t * 256;
        int r = f >> 4;
        int dq = (f & 15) << 2;
        float4 v = *reinterpret_cast<const float4*>(
            &base[(size_t)(q0 + r) * QKVW + hc + dq]);
        Qs[r][dq + 0] = v.x * 0.125f;
        Qs[r][dq + 1] = v.y * 0.125f;
        Qs[r][dq + 2] = v.z * 0.125f;
        Qs[r][dq + 3] = v.w * 0.125f;
    }

    float m[4], lsum[4], acc[4][2];
#pragma unroll
    for (int i = 0; i < 4; i++) {
        m[i] = -1e30f; lsum[i] = 0.0f; acc[i][0] = 0.0f; acc[i][1] = 0.0f;
    }

    for (int kt = 0; kt < T_; kt += 64) {
        __syncthreads();
#pragma unroll
        for (int t = 0; t < 4; t++) {
            int f = tid + t * 256;
            int r = f >> 4;
            int dq = (f & 15) << 2;
            float4 v = *reinterpret_cast<const float4*>(
                &base[(size_t)(kt + r) * QKVW + E_ + hc + dq]);
            KV[r][dq + 0] = v.x; KV[r][dq + 1] = v.y;
            KV[r][dq + 2] = v.z; KV[r][dq + 3] = v.w;
        }
        __syncthreads();

        float s[4][2];
#pragma unroll
        for (int i = 0; i < 4; i++) { s[i][0] = 0.0f; s[i][1] = 0.0f; }
#pragma unroll 8
        for (int d = 0; d < 64; d++) {
            float k0v = KV[lane][d];
            float k1v = KV[lane + 32][d];
#pragma unroll
            for (int i = 0; i < 4; i++) {
                float q = Qs[r0 + i][d];
                s[i][0] = fmaf(q, k0v, s[i][0]);
                s[i][1] = fmaf(q, k1v, s[i][1]);
            }
        }

#pragma unroll
        for (int i = 0; i < 4; i++) {
            float rm = fmaxf(s[i][0], s[i][1]);
#pragma unroll
            for (int o = 16; o > 0; o >>= 1)
                rm = fmaxf(rm, __shfl_xor_sync(0xffffffffu, rm, o));
            float mnew = fmaxf(m[i], rm);
            float corr = __expf(m[i] - mnew);
            float p0 = __expf(s[i][0] - mnew);
            float p1 = __expf(s[i][1] - mnew);
            float ps = p0 + p1;
#pragma unroll
            for (int o = 16; o > 0; o >>= 1)
                ps += __shfl_xor_sync(0xffffffffu, ps, o);
            lsum[i] = lsum[i] * corr + ps;
            acc[i][0] *= corr;
            acc[i][1] *= corr;
            Ps[r0 + i][lane] = p0;
            Ps[r0 + i][lane + 32] = p1;
            m[i] = mnew;
        }
        __syncthreads();

#pragma unroll
        for (int t = 0; t < 4; t++) {
            int f = tid + t * 256;
            int r = f >> 4;
            int dq = (f & 15) << 2;
            float4 v = *reinterpret_cast<const float4*>(
                &base[(size_t)(kt + r) * QKVW + 2 * E_ + hc + dq]);
            KV[r][dq + 0] = v.x; KV[r][dq + 1] = v.y;
            KV[r][dq + 2] = v.z; KV[r][dq + 3] = v.w;
        }
        __syncthreads();

#pragma unroll 8
        for (int k = 0; k < 64; k++) {
            float v0 = KV[k][lane];
            float v1 = KV[k][lane + 32];
#pragma unroll
            for (int i = 0; i < 4; i++) {
                float p = Ps[r0 + i][k];
                acc[i][0] = fmaf(p, v0, acc[i][0]);
                acc[i][1] = fmaf(p, v1, acc[i][1]);
            }
        }
    }

#pragma unroll
    for (int i = 0; i < 4; i++) {
        float inv = 1.0f / lsum[i];
        size_t orow = ((size_t)b * T_ + q0 + r0 + i) * E_ + hc;
        out[orow + lane]      = acc[i][0] * inv;
        out[orow + lane + 32] = acc[i][1] * inv;
    }
}

// ---------------------------------------------------------------------------
// Orchestration
// ---------------------------------------------------------------------------
extern "C" void kernel_launch(void* const* d_in, const int* in_sizes, int n_in,
                              void* d_out, int out_size)
{
    const float* x_in  = (const float*)d_in[0];
    const float* Wqkv  = (const float*)d_in[1];
    const float* bqkv  = (const float*)d_in[2];
    const float* Wproj = (const float*)d_in[3];
    const float* bproj = (const float*)d_in[4];
    const float* W1    = (const float*)d_in[5];
    const float* b1    = (const float*)d_in[6];
    const float* W2    = (const float*)d_in[7];
    const float* b2    = (const float*)d_in[8];
    float* out = (float*)d_out;

    float *gx, *gqkv, *gattn, *gh;
    cudaGetSymbolAddress((void**)&gx, g_x);
    cudaGetSymbolAddress((void**)&gqkv, g_qkv);
    cudaGetSymbolAddress((void**)&gattn, g_attn);
    cudaGetSymbolAddress((void**)&gh, g_h);

    dim3 blk(256);
    for (int l = 0; l < L_; l++) {
        const float* xcur = (l == 0) ? x_in : gx;

        gemm_mma<0, false><<<dim3(QKVW / 128, M_ / 128), blk>>>(
            xcur, Wqkv + (size_t)l * E_ * QKVW, bqkv + (size_t)l * QKVW,
            nullptr, gqkv, M_, QKVW, E_);

        attn_kernel<<<dim3(T_ / 32, B_ * H_), blk>>>(gqkv, gattn);

        gemm_mma<0, true><<<dim3(E_ / 128, M_ / 128), blk>>>(
            gattn, Wproj + (size_t)l * E_ * E_, bproj + (size_t)l * E_,
            xcur, gx, M_, E_, E_);

        gemm_mma<1, false><<<dim3(FFDIM / 128, M_ / 128), blk>>>(
            gx, W1 + (size_t)l * E_ * FFDIM, b1 + (size_t)l * FFDIM,
            nullptr, gh, M_, FFDIM, E_);

        float* dst = (l == L_ - 1) ? out : gx;
        gemm_mma<0, true><<<dim3(E_ / 128, M_ / 128), blk>>>(
            gh, W2 + (size_t)l * FFDIM * E_, b2 + (size_t)l * E_,
            gx, dst, M_, E_, FFDIM);
    }
}

// round 3
// speedup vs baseline: 2.7176x; 1.6944x over previous
#include <cuda_runtime.h>
#include <cuda_bf16.h>
#include <math.h>

// Problem constants
constexpr int B_ = 2, T_ = 2048, E_ = 1024, H_ = 16, FFDIM = 4096, L_ = 4;
constexpr int M_ = B_ * T_;           // 4096 token rows
constexpr int QKVW = 3 * E_;          // 3072

// Scratch (device globals; no allocations allowed)
__device__ float g_x[M_ * E_];        // residual stream
__device__ float g_qkv[M_ * 3 * E_];  // fused qkv
__device__ float g_attn[M_ * E_];     // attention output (pre-proj)
__device__ float g_h[M_ * FFDIM];     // MLP hidden

__device__ __forceinline__ float gelu_tanh(float x) {
    float x3 = x * x * x;
    return 0.5f * x * (1.0f + tanhf(0.7978845608028654f * (x + 0.044715f * x3)));
}

// pack two fp32 into bf16x2 (first arg -> low 16 bits / element 0 in memory)
__device__ __forceinline__ unsigned pack2(float lo, float hi) {
    unsigned r;
    asm("cvt.rn.bf16x2.f32 %0, %1, %2;" : "=r"(r) : "f"(hi), "f"(lo));
    return r;
}

__device__ __forceinline__ void ldmx4(unsigned* r, unsigned addr) {
    asm volatile("ldmatrix.sync.aligned.m8n8.x4.shared.b16 {%0,%1,%2,%3}, [%4];"
        : "=r"(r[0]), "=r"(r[1]), "=r"(r[2]), "=r"(r[3]) : "r"(addr));
}
__device__ __forceinline__ void ldmx4t(unsigned* r, unsigned addr) {
    asm volatile("ldmatrix.sync.aligned.m8n8.x4.trans.shared.b16 {%0,%1,%2,%3}, [%4];"
        : "=r"(r[0]), "=r"(r[1]), "=r"(r[2]), "=r"(r[3]) : "r"(addr));
}
__device__ __forceinline__ void mma16816(float* d, const unsigned* a, const unsigned* b) {
    asm volatile("mma.sync.aligned.m16n8k16.row.col.f32.bf16.bf16.f32 "
        "{%0,%1,%2,%3}, {%4,%5,%6,%7}, {%8,%9}, {%0,%1,%2,%3};"
        : "+f"(d[0]), "+f"(d[1]), "+f"(d[2]), "+f"(d[3])
        : "r"(a[0]), "r"(a[1]), "r"(a[2]), "r"(a[3]), "r"(b[0]), "r"(b[1]));
}

// split a float4 into hi/lo bf16x2 pairs
__device__ __forceinline__ void split4(float4 v, unsigned& h0, unsigned& h1,
                                       unsigned& l0, unsigned& l1) {
    h0 = pack2(v.x, v.y); h1 = pack2(v.z, v.w);
    float rx = __uint_as_float(h0 << 16), ry = __uint_as_float(h0 & 0xFFFF0000u);
    float rz = __uint_as_float(h1 << 16), rw = __uint_as_float(h1 & 0xFFFF0000u);
    l0 = pack2(v.x - rx, v.y - ry); l1 = pack2(v.z - rz, v.w - rw);
}

// ---------------------------------------------------------------------------
// Tensor-core GEMM with bf16 3-term split (hi*hi + hi*lo + lo*hi), fp32 accum.
// (unchanged from round 2 — verified)
// ---------------------------------------------------------------------------
template <int ACT, bool RES>
__global__ void __launch_bounds__(256) gemm_mma(
    const float* __restrict__ A, const float* __restrict__ W,
    const float* __restrict__ bias, const float* __restrict__ res,
    float* __restrict__ C, int M, int N, int K)
{
    __shared__ __align__(16) unsigned short As_h[128][40];
    __shared__ __align__(16) unsigned short As_l[128][40];
    __shared__ __align__(16) unsigned short Bs_h[32][136];
    __shared__ __align__(16) unsigned short Bs_l[32][136];

    const int bm = blockIdx.y * 128;
    const int bn = blockIdx.x * 128;
    const int tid = threadIdx.x;
    const int lane = tid & 31;
    const int warp = tid >> 5;
    const int wm = (warp >> 2) * 64;
    const int wn = (warp & 3) * 32;

    float acc[4][4][4];
#pragma unroll
    for (int i = 0; i < 4; i++)
#pragma unroll
        for (int j = 0; j < 4; j++)
#pragma unroll
            for (int t = 0; t < 4; t++) acc[i][j][t] = 0.0f;

    float4 Ar[4], Br[4];

    auto load_tile = [&](int k0) {
#pragma unroll
        for (int i = 0; i < 4; i++) {
            int f = tid + 256 * i;
            int r = f >> 3, kc = (f & 7) << 2;
            Ar[i] = *reinterpret_cast<const float4*>(&A[(size_t)(bm + r) * K + k0 + kc]);
        }
#pragma unroll
        for (int i = 0; i < 4; i++) {
            int f = tid + 256 * i;
            int r = f >> 5, nc = (f & 31) << 2;
            Br[i] = *reinterpret_cast<const float4*>(&W[(size_t)(k0 + r) * N + bn + nc]);
        }
    };

    auto stage_tile = [&]() {
#pragma unroll
        for (int i = 0; i < 4; i++) {
            int f = tid + 256 * i;
            int r = f >> 3, kc = (f & 7) << 2;
            unsigned h0, h1, l0, l1;
            split4(Ar[i], h0, h1, l0, l1);
            *reinterpret_cast<uint2*>(&As_h[r][kc]) = make_uint2(h0, h1);
            *reinterpret_cast<uint2*>(&As_l[r][kc]) = make_uint2(l0, l1);
        }
#pragma unroll
        for (int i = 0; i < 4; i++) {
            int f = tid + 256 * i;
            int r = f >> 5, nc = (f & 31) << 2;
            unsigned h0, h1, l0, l1;
            split4(Br[i], h0, h1, l0, l1);
            *reinterpret_cast<uint2*>(&Bs_h[r][nc]) = make_uint2(h0, h1);
            *reinterpret_cast<uint2*>(&Bs_l[r][nc]) = make_uint2(l0, l1);
        }
    };

    const int nstages = K >> 5;
    load_tile(0);
    stage_tile();
    __syncthreads();

    for (int s = 0; s < nstages; s++) {
        if (s + 1 < nstages) load_tile((s + 1) << 5);

#pragma unroll
        for (int ks = 0; ks < 32; ks += 16) {
            unsigned bh[2][4], bl[2][4];
#pragma unroll
            for (int g = 0; g < 2; g++) {
                unsigned a0 = (unsigned)__cvta_generic_to_shared(
                    &Bs_h[ks + (lane & 15)][wn + g * 16 + ((lane >> 4) << 3)]);
                ldmx4t(bh[g], a0);
                unsigned a1 = (unsigned)__cvta_generic_to_shared(
                    &Bs_l[ks + (lane & 15)][wn + g * 16 + ((lane >> 4) << 3)]);
                ldmx4t(bl[g], a1);
            }
#pragma unroll
            for (int ma = 0; ma < 4; ma++) {
                unsigned ah[4], al[4];
                unsigned a0 = (unsigned)__cvta_generic_to_shared(
                    &As_h[wm + ma * 16 + (lane & 15)][ks + ((lane >> 4) << 3)]);
                ldmx4(ah, a0);
                unsigned a1 = (unsigned)__cvta_generic_to_shared(
                    &As_l[wm + ma * 16 + (lane & 15)][ks + ((lane >> 4) << 3)]);
                ldmx4(al, a1);
#pragma unroll
                for (int na = 0; na < 4; na++) {
                    const unsigned* bhp = &bh[na >> 1][(na & 1) * 2];
                    const unsigned* blp = &bl[na >> 1][(na & 1) * 2];
                    mma16816(acc[ma][na], ah, bhp);
                    mma16816(acc[ma][na], ah, blp);
                    mma16816(acc[ma][na], al, bhp);
                }
            }
        }

        if (s + 1 < nstages) {
            __syncthreads();
            stage_tile();
            __syncthreads();
        }
    }

#pragma unroll
    for (int ma = 0; ma < 4; ma++) {
        int r0 = bm + wm + ma * 16 + (lane >> 2);
#pragma unroll
        for (int na = 0; na < 4; na++) {
            int c0 = bn + wn + na * 8 + ((lane & 3) << 1);
            float b0v = bias[c0], b1v = bias[c0 + 1];
            float v00 = acc[ma][na][0] + b0v, v01 = acc[ma][na][1] + b1v;
            float v10 = acc[ma][na][2] + b0v, v11 = acc[ma][na][3] + b1v;
            if (ACT == 1) {
                v00 = gelu_tanh(v00); v01 = gelu_tanh(v01);
                v10 = gelu_tanh(v10); v11 = gelu_tanh(v11);
            }
            if (RES) {
                v00 += res[(size_t)r0 * N + c0];
                v01 += res[(size_t)r0 * N + c0 + 1];
                v10 += res[(size_t)(r0 + 8) * N + c0];
                v11 += res[(size_t)(r0 + 8) * N + c0 + 1];
            }
            *reinterpret_cast<float2*>(&C[(size_t)r0 * N + c0]) = make_float2(v00, v01);
            *reinterpret_cast<float2*>(&C[(size_t)(r0 + 8) * N + c0]) = make_float2(v10, v11);
        }
    }
}

// ---------------------------------------------------------------------------
// Tensor-core flash attention, bf16 3-term split on both GEMMs, fp32 softmax.
// Q tile 128 rows (8 warps x m16), kv tiles of 64. P stays in registers:
// S accumulator fragments are reinterpreted as A fragments for P@V.
// ---------------------------------------------------------------------------
__global__ void __launch_bounds__(256) attn_mma(
    const float* __restrict__ qkv, float* __restrict__ out)
{
    // union: Q staging [128][72] hi+lo == K/V hi/lo buffers [64][72] x4
    __shared__ __align__(16) unsigned short sm[18432];

    const int b = blockIdx.y >> 4;
    const int h = blockIdx.y & 15;
    const int q0 = blockIdx.x * 128;
    const int tid = threadIdx.x;
    const int lane = tid & 31;
    const int warp = tid >> 5;
    const float* base = qkv + (size_t)b * T_ * QKVW;
    const int hc = h * 64;

    // ---- stage Q (scaled by 1/sqrt(64)=0.125) and preload A-fragments ----
    unsigned short* Qh = sm;          // [128][72]
    unsigned short* Ql = sm + 9216;
#pragma unroll
    for (int i = 0; i < 8; i++) {
        int f = tid + 256 * i;        // 2048 float4 = 128 rows x 16
        int r = f >> 4;
        int c = (f & 15) << 2;
        float4 v = *reinterpret_cast<const float4*>(
            &base[(size_t)(q0 + r) * QKVW + hc + c]);
        v.x *= 0.125f; v.y *= 0.125f; v.z *= 0.125f; v.w *= 0.125f;
        unsigned h0, h1, l0, l1;
        split4(v, h0, h1, l0, l1);
        *reinterpret_cast<uint2*>(&Qh[r * 72 + c]) = make_uint2(h0, h1);
        *reinterpret_cast<uint2*>(&Ql[r * 72 + c]) = make_uint2(l0, l1);
    }
    __syncthreads();

    unsigned qh[4][4], ql[4][4];
#pragma unroll
    for (int ks = 0; ks < 4; ks++) {
        int row = warp * 16 + (lane & 15);
        int col = ks * 16 + ((lane >> 4) << 3);
        ldmx4(qh[ks], (unsigned)__cvta_generic_to_shared(&Qh[row * 72 + col]));
        ldmx4(ql[ks], (unsigned)__cvta_generic_to_shared(&Ql[row * 72 + col]));
    }
    __syncthreads();   // Q fragments in regs; smem free for K/V

    unsigned short* Kh = sm;           // [64][72]
    unsigned short* Kl = sm + 4608;
    unsigned short* Vh = sm + 9216;
    unsigned short* Vl = sm + 13824;

    float oacc[8][4];
#pragma unroll
    for (int t = 0; t < 8; t++)
#pragma unroll
        for (int j = 0; j < 4; j++) oacc[t][j] = 0.0f;
    float m0 = -1e30f, m1 = -1e30f, lsum0 = 0.0f, lsum1 = 0.0f;

    float4 Kr[4], Vr[4];
    auto load_kv = [&](int kt) {
#pragma unroll
        for (int i = 0; i < 4; i++) {
            int f = tid + 256 * i;     // 1024 float4 = 64 rows x 16
            int r = f >> 4, c = (f & 15) << 2;
            Kr[i] = *reinterpret_cast<const float4*>(
                &base[(size_t)(kt + r) * QKVW + E_ + hc + c]);
            Vr[i] = *reinterpret_cast<const float4*>(
                &base[(size_t)(kt + r) * QKVW + 2 * E_ + hc + c]);
        }
    };
    auto stage_kv = [&]() {
#pragma unroll
        for (int i = 0; i < 4; i++) {
            int f = tid + 256 * i;
            int r = f >> 4, c = (f & 15) << 2;
            unsigned h0, h1, l0, l1;
            split4(Kr[i], h0, h1, l0, l1);
            *reinterpret_cast<uint2*>(&Kh[r * 72 + c]) = make_uint2(h0, h1);
            *reinterpret_cast<uint2*>(&Kl[r * 72 + c]) = make_uint2(l0, l1);
            split4(Vr[i], h0, h1, l0, l1);
            *reinterpret_cast<uint2*>(&Vh[r * 72 + c]) = make_uint2(h0, h1);
            *reinterpret_cast<uint2*>(&Vl[r * 72 + c]) = make_uint2(l0, l1);
        }
    };

    load_kv(0);
    stage_kv();
    __syncthreads();

    constexpr int NIT = T_ / 64;
    for (int it = 0; it < NIT; it++) {
        if (it + 1 < NIT) load_kv((it + 1) * 64);

        // ---- S = Q @ K^T (m16 x kv64, 3-term split) ----
        float sacc[8][4];
#pragma unroll
        for (int t = 0; t < 8; t++)
#pragma unroll
            for (int j = 0; j < 4; j++) sacc[t][j] = 0.0f;

#pragma unroll
        for (int ks = 0; ks < 4; ks++) {
#pragma unroll
            for (int g = 0; g < 4; g++) {
                int row = g * 16 + ((lane >> 4) << 3) + (lane & 7);
                int col = ks * 16 + (((lane >> 3) & 1) << 3);
                unsigned bh[4], bl[4];
                ldmx4(bh, (unsigned)__cvta_generic_to_shared(&Kh[row * 72 + col]));
                ldmx4(bl, (unsigned)__cvta_generic_to_shared(&Kl[row * 72 + col]));
                mma16816(sacc[2 * g],     qh[ks], &bh[0]);
                mma16816(sacc[2 * g],     qh[ks], &bl[0]);
                mma16816(sacc[2 * g],     ql[ks], &bh[0]);
                mma16816(sacc[2 * g + 1], qh[ks], &bh[2]);
                mma16816(sacc[2 * g + 1], qh[ks], &bl[2]);
                mma16816(sacc[2 * g + 1], ql[ks], &bh[2]);
            }
        }

        // ---- online softmax (rows r0=lane>>2 and r0+8) ----
        float mx0 = -1e30f, mx1 = -1e30f;
#pragma unroll
        for (int t = 0; t < 8; t++) {
            mx0 = fmaxf(mx0, fmaxf(sacc[t][0], sacc[t][1]));
            mx1 = fmaxf(mx1, fmaxf(sacc[t][2], sacc[t][3]));
        }
        mx0 = fmaxf(mx0, __shfl_xor_sync(0xffffffffu, mx0, 1));
        mx0 = fmaxf(mx0, __shfl_xor_sync(0xffffffffu, mx0, 2));
        mx1 = fmaxf(mx1, __shfl_xor_sync(0xffffffffu, mx1, 1));
        mx1 = fmaxf(mx1, __shfl_xor_sync(0xffffffffu, mx1, 2));
        float mn0 = fmaxf(m0, mx0), mn1 = fmaxf(m1, mx1);
        float c0 = __expf(m0 - mn0), c1 = __expf(m1 - mn1);
        m0 = mn0; m1 = mn1;
        float s0 = 0.0f, s1 = 0.0f;
#pragma unroll
        for (int t = 0; t < 8; t++) {
            sacc[t][0] = __expf(sacc[t][0] - m0);
            sacc[t][1] = __expf(sacc[t][1] - m0);
            sacc[t][2] = __expf(sacc[t][2] - m1);
            sacc[t][3] = __expf(sacc[t][3] - m1);
            s0 += sacc[t][0] + sacc[t][1];
            s1 += sacc[t][2] + sacc[t][3];
        }
        s0 += __shfl_xor_sync(0xffffffffu, s0, 1);
        s0 += __shfl_xor_sync(0xffffffffu, s0, 2);
        s1 += __shfl_xor_sync(0xffffffffu, s1, 1);
        s1 += __shfl_xor_sync(0xffffffffu, s1, 2);
        lsum0 = lsum0 * c0 + s0;
        lsum1 = lsum1 * c1 + s1;
#pragma unroll
        for (int t = 0; t < 8; t++) {
            oacc[t][0] *= c0; oacc[t][1] *= c0;
            oacc[t][2] *= c1; oacc[t][3] *= c1;
        }

        // ---- O += P @ V (P from registers, 3-term split) ----
#pragma unroll
        for (int kk = 0; kk < 4; kk++) {
            unsigned ph[4], pl[4];
            ph[0] = pack2(sacc[2 * kk][0], sacc[2 * kk][1]);
            ph[1] = pack2(sacc[2 * kk][2], sacc[2 * kk][3]);
            ph[2] = pack2(sacc[2 * kk + 1][0], sacc[2 * kk + 1][1]);
            ph[3] = pack2(sacc[2 * kk + 1][2], sacc[2 * kk + 1][3]);
#pragma unroll
            for (int u = 0; u < 4; u++) {
                const float* p = sacc[2 * kk + (u >> 1)];
                int o = (u & 1) * 2;
                float rx = __uint_as_float(ph[u] << 16);
                float ry = __uint_as_float(ph[u] & 0xFFFF0000u);
                pl[u] = pack2(p[o] - rx, p[o + 1] - ry);
            }
#pragma unroll
            for (int g = 0; g < 4; g++) {
                int row = kk * 16 + (((lane >> 3) & 1) << 3) + (lane & 7);
                int col = g * 16 + ((lane >> 4) << 3);
                unsigned vh[4], vl[4];
                ldmx4t(vh, (unsigned)__cvta_generic_to_shared(&Vh[row * 72 + col]));
                ldmx4t(vl, (unsigned)__cvta_generic_to_shared(&Vl[row * 72 + col]));
                mma16816(oacc[2 * g],     ph, &vh[0]);
                mma16816(oacc[2 * g],     ph, &vl[0]);
                mma16816(oacc[2 * g],     pl, &vh[0]);
                mma16816(oacc[2 * g + 1], ph, &vh[2]);
                mma16816(oacc[2 * g + 1], ph, &vl[2]);
                mma16816(oacc[2 * g + 1], pl, &vh[2]);
            }
        }

        if (it + 1 < NIT) {
            __syncthreads();
            stage_kv();
            __syncthreads();
        }
    }

    // ---- normalize + write ----
    float inv0 = 1.0f / lsum0, inv1 = 1.0f / lsum1;
    int r0 = q0 + warp * 16 + (lane >> 2);
#pragma unroll
    for (int t = 0; t < 8; t++) {
        int col = hc + t * 8 + ((lane & 3) << 1);
        *reinterpret_cast<float2*>(&out[((size_t)b * T_ + r0) * E_ + col]) =
            make_float2(oacc[t][0] * inv0, oacc[t][1] * inv0);
        *reinterpret_cast<float2*>(&out[((size_t)b * T_ + r0 + 8) * E_ + col]) =
            make_float2(oacc[t][2] * inv1, oacc[t][3] * inv1);
    }
}

// ---------------------------------------------------------------------------
// Orchestration
// ---------------------------------------------------------------------------
extern "C" void kernel_launch(void* const* d_in, const int* in_sizes, int n_in,
                              void* d_out, int out_size)
{
    const float* x_in  = (const float*)d_in[0];
    const float* Wqkv  = (const float*)d_in[1];
    const float* bqkv  = (const float*)d_in[2];
    const float* Wproj = (const float*)d_in[3];
    const float* bproj = (const float*)d_in[4];
    const float* W1    = (const float*)d_in[5];
    const float* b1    = (const float*)d_in[6];
    const float* W2    = (const float*)d_in[7];
    const float* b2    = (const float*)d_in[8];
    float* out = (float*)d_out;

    float *gx, *gqkv, *gattn, *gh;
    cudaGetSymbolAddress((void**)&gx, g_x);
    cudaGetSymbolAddress((void**)&gqkv, g_qkv);
    cudaGetSymbolAddress((void**)&gattn, g_attn);
    cudaGetSymbolAddress((void**)&gh, g_h);

    dim3 blk(256);
    for (int l = 0; l < L_; l++) {
        const float* xcur = (l == 0) ? x_in : gx;

        gemm_mma<0, false><<<dim3(QKVW / 128, M_ / 128), blk>>>(
            xcur, Wqkv + (size_t)l * E_ * QKVW, bqkv + (size_t)l * QKVW,
            nullptr, gqkv, M_, QKVW, E_);

        attn_mma<<<dim3(T_ / 128, B_ * H_), blk>>>(gqkv, gattn);

        gemm_mma<0, true><<<dim3(E_ / 128, M_ / 128), blk>>>(
            gattn, Wproj + (size_t)l * E_ * E_, bproj + (size_t)l * E_,
            xcur, gx, M_, E_, E_);

        gemm_mma<1, false><<<dim3(FFDIM / 128, M_ / 128), blk>>>(
            gx, W1 + (size_t)l * E_ * FFDIM, b1 + (size_t)l * FFDIM,
            nullptr, gh, M_, FFDIM, E_);

        float* dst = (l == L_ - 1) ? out : gx;
        gemm_mma<0, true><<<dim3(E_ / 128, M_ / 128), blk>>>(
            gh, W2 + (size_t)l * FFDIM * E_, b2 + (size_t)l * E_,
            gx, dst, M_, E_, FFDIM);
    }
}